// round 14
// baseline (speedup 1.0000x reference)
#include <cuda_runtime.h>
#include <math.h>

#define T_   2048
#define B_   512
#define IN_  32
#define H_   256
#define ROWS_ 4
#define NBLK_ (B_ / ROWS_)
#define THREADS_ 512
#define DT_C  0.1f
#define EPS_C 1e-5f

typedef unsigned long long u64;

// Repacked fp32 weights: 6 matrices [H x H] -> [H/4][H] float4:
// g_Wp[(m*64 + k4)*256 + j] = { W[4k4+0][j], W[4k4+1][j], W[4k4+2][j], W[4k4+3][j] }
// Order m: Wattn0, Wrec0, Wattn1, Win1, Wskip, Wrec1
#define MATP_ (64 * 256)
__device__ float4 g_Wp[6 * MATP_];

// Dynamic SMEM layout (float4 units):
//  [0,256)      h0s       [256,512)   h1s      [512,768)   p1s
//  [768,1024)   gbuf0     [1024,1280) gbuf1    [1280,1536) h0ns
//  [1536,1792)  tbuf
//  [1792,4864)  pb[12][256]   (3 regions x 4 quarters)
//  [4864,4896)  xts       [4896,4928) p0s      [4928,4936) redbuf
//  then floats: params[16][256], wev0s[64], scal[16]
#define SMEM_F4_  4936
#define SMEM_BYTES_ (SMEM_F4_ * 16 + 4096 * 4 + 64 * 4 + 16 * 4)

__device__ __forceinline__ float sigf(float z) { return 1.0f / (1.0f + expf(-z)); }

__device__ __forceinline__ u64 pack_dup(float w) {
    u64 r;
    unsigned int u = __float_as_uint(w);
    asm("mov.b64 %0, {%1, %1};" : "=l"(r) : "r"(u));
    return r;
}
__device__ __forceinline__ void unpack2(u64 v, float& a, float& b) {
    unsigned int lo, hi;
    asm("mov.b64 {%0, %1}, %2;" : "=r"(lo), "=r"(hi) : "l"(v));
    a = __uint_as_float(lo); b = __uint_as_float(hi);
}
__device__ __forceinline__ void fma2(u64& acc, u64 a, u64 b) {
    asm("fma.rn.f32x2 %0, %1, %2, %0;" : "+l"(acc) : "l"(a), "l"(b));
}
#define BAR256() asm volatile("bar.sync 1, 256;" ::: "memory")

__global__ void pack_weights(const float* __restrict__ W0, const float* __restrict__ W1,
                             const float* __restrict__ W2, const float* __restrict__ W3,
                             const float* __restrict__ W4, const float* __restrict__ W5)
{
    int idx = blockIdx.x * blockDim.x + threadIdx.x;
    if (idx >= 6 * MATP_) return;
    const float* Ws[6] = {W0, W1, W2, W3, W4, W5};
    int m  = idx / MATP_;
    int r  = idx - m * MATP_;
    int k4 = r >> 8;
    int j  = r & 255;
    const float* W = Ws[m];
    g_Wp[idx] = make_float4(W[(4 * k4 + 0) * H_ + j], W[(4 * k4 + 1) * H_ + j],
                            W[(4 * k4 + 2) * H_ + j], W[(4 * k4 + 3) * H_ + j]);
}

// Quarter-K (64 k) matvec partial for 4 columns (jg, jg+64, jg+128, jg+192)
// sharing the state loads. Per-column accumulation order identical to mv2
// (ascending k, fp32x2 pairs) -> bit-identical partials.
__device__ __forceinline__ void mv4(const float4* __restrict__ wp,
                                    const float4* st, float4 r[4])
{
    u64 a01[4], a23[4];
    #pragma unroll
    for (int c = 0; c < 4; ++c) { a01[c] = 0ull; a23[c] = 0ull; }
    const ulonglong2* sp = (const ulonglong2*)st;
    #pragma unroll
    for (int k4 = 0; k4 < 16; ++k4) {
        float4 w0 = __ldg(&wp[k4 * H_]);
        float4 w1 = __ldg(&wp[k4 * H_ + 64]);
        float4 w2 = __ldg(&wp[k4 * H_ + 128]);
        float4 w3 = __ldg(&wp[k4 * H_ + 192]);
        ulonglong2 s0 = sp[4 * k4 + 0];
        ulonglong2 s1 = sp[4 * k4 + 1];
        ulonglong2 s2 = sp[4 * k4 + 2];
        ulonglong2 s3 = sp[4 * k4 + 3];
        u64 d;
        d = pack_dup(w0.x); fma2(a01[0], d, s0.x); fma2(a23[0], d, s0.y);
        d = pack_dup(w1.x); fma2(a01[1], d, s0.x); fma2(a23[1], d, s0.y);
        d = pack_dup(w2.x); fma2(a01[2], d, s0.x); fma2(a23[2], d, s0.y);
        d = pack_dup(w3.x); fma2(a01[3], d, s0.x); fma2(a23[3], d, s0.y);
        d = pack_dup(w0.y); fma2(a01[0], d, s1.x); fma2(a23[0], d, s1.y);
        d = pack_dup(w1.y); fma2(a01[1], d, s1.x); fma2(a23[1], d, s1.y);
        d = pack_dup(w2.y); fma2(a01[2], d, s1.x); fma2(a23[2], d, s1.y);
        d = pack_dup(w3.y); fma2(a01[3], d, s1.x); fma2(a23[3], d, s1.y);
        d = pack_dup(w0.z); fma2(a01[0], d, s2.x); fma2(a23[0], d, s2.y);
        d = pack_dup(w1.z); fma2(a01[1], d, s2.x); fma2(a23[1], d, s2.y);
        d = pack_dup(w2.z); fma2(a01[2], d, s2.x); fma2(a23[2], d, s2.y);
        d = pack_dup(w3.z); fma2(a01[3], d, s2.x); fma2(a23[3], d, s2.y);
        d = pack_dup(w0.w); fma2(a01[0], d, s3.x); fma2(a23[0], d, s3.y);
        d = pack_dup(w1.w); fma2(a01[1], d, s3.x); fma2(a23[1], d, s3.y);
        d = pack_dup(w2.w); fma2(a01[2], d, s3.x); fma2(a23[2], d, s3.y);
        d = pack_dup(w3.w); fma2(a01[3], d, s3.x); fma2(a23[3], d, s3.y);
    }
    #pragma unroll
    for (int c = 0; c < 4; ++c) {
        unpack2(a01[c], r[c].x, r[c].y);
        unpack2(a23[c], r[c].z, r[c].w);
    }
}

__global__ void __launch_bounds__(THREADS_, 1)
liquid_kernel(const float* __restrict__ x,
              const float* __restrict__ Win0,  const float* __restrict__ bin0,
              const float* __restrict__ brec0, const float* __restrict__ battn0,
              const float* __restrict__ Wev0,  const float* __restrict__ bev0,
              const float* __restrict__ tau0,  const float* __restrict__ gamma0,
              const float* __restrict__ beta0,
              const float* __restrict__ bin1,  const float* __restrict__ brec1,
              const float* __restrict__ battn1,
              const float* __restrict__ Wev1,  const float* __restrict__ bev1,
              const float* __restrict__ tau1,  const float* __restrict__ gamma1,
              const float* __restrict__ beta1,
              const float* __restrict__ bskip,
              const float* __restrict__ Wout,  const float* __restrict__ bout,
              float* __restrict__ out)
{
    extern __shared__ float4 smem4[];
    float4* h0s   = smem4;
    float4* h1s   = smem4 + 256;
    float4* p1s   = smem4 + 512;
    float4* gbuf0 = smem4 + 768;
    float4* gbuf1 = smem4 + 1024;
    float4* h0ns  = smem4 + 1280;
    float4* tbuf  = smem4 + 1536;
    float4* pb    = smem4 + 1792;            // [12][256]
    float4* xts   = smem4 + 4864;            // 32
    float4* p0s   = smem4 + 4896;            // 32
    float4* redbuf = smem4 + 4928;           // 8
    float*  params = (float*)(smem4 + SMEM_F4_);  // 16*256
    float*  wev0s  = params + 4096;               // 64
    float*  scal   = wev0s + 64;                  // ew0[4], ew1[4], mu[4], rs[4]

    const int tid   = threadIdx.x;
    const int lane  = tid & 31;
    const int wid   = tid >> 5;
    const int mvsel = tid >> 8;         // which matvec of the phase pair
    const int rq    = (tid >> 6) & 3;   // K quarter
    const int jg    = tid & 63;         // column group (cols jg+64c)
    const int b0    = blockIdx.x * ROWS_;

    const float c_bev0 = bev0[0], c_bev1 = bev1[0], c_bout = bout[0];

    // weight bases for this thread's slot in each phase
    const int qj = rq * 16 * H_ + jg;
    const float4* P1w = g_Wp + (mvsel ? 2 : 0) * MATP_ + qj;  // attn1 : attn0
    const float4* P2w = g_Wp + (mvsel ? 5 : 1) * MATP_ + qj;  // rec1  : rec0
    const float4* P3w = g_Wp + (mvsel ? 4 : 3) * MATP_ + qj;  // skip  : inp1
    // state bases per phase
    const float4* P1st = (mvsel ? h1s : h0s) + rq * 64;
    const float4* P2st = (mvsel ? gbuf1 : gbuf0) + rq * 64;
    const float4* P3st = h0ns + rq * 64;
    // pb write bases per phase: P1: attn0->slots0-3, attn1->4-7;
    // P2: rec0->0-3, rec1->8-11; P3: inp1->0-3, skip->4-7.
    float4* P1pb = pb + ((mvsel ? 4 : 0) + rq) * 256 + jg;
    float4* P2pb = pb + ((mvsel ? 8 : 0) + rq) * 256 + jg;
    float4* P3pb = pb + ((mvsel ? 4 : 0) + rq) * 256 + jg;

    const float4 z4 = make_float4(0.f, 0.f, 0.f, 0.f);
    if (tid < 256) {
        int j = tid;
        params[0 * 256 + j]  = battn0[j];
        params[1 * 256 + j]  = brec0[j];
        params[2 * 256 + j]  = bin0[j];
        params[3 * 256 + j]  = battn1[j];
        params[4 * 256 + j]  = brec1[j];
        params[5 * 256 + j]  = bin1[j];
        params[6 * 256 + j]  = bskip[j];
        params[7 * 256 + j]  = gamma0[j];
        params[8 * 256 + j]  = beta0[j];
        params[9 * 256 + j]  = gamma1[j];
        params[10 * 256 + j] = beta1[j];
        params[11 * 256 + j] = DT_C / fminf(fmaxf(tau0[j], 0.1f), 10.0f);
        params[12 * 256 + j] = DT_C / fminf(fmaxf(tau1[j], 0.1f), 10.0f);
        params[13 * 256 + j] = Wev1[j];
        params[14 * 256 + j] = Wev1[H_ + j];
        params[15 * 256 + j] = Wout[j];
        h0s[j] = z4; h1s[j] = z4; p1s[j] = z4;
    }
    if (tid < 2 * IN_) wev0s[tid] = Wev0[tid];
    if (tid < IN_) {
        p0s[tid] = z4;
        float4 v;
        v.x = x[((size_t)(b0 + 0) * T_) * IN_ + tid];
        v.y = x[((size_t)(b0 + 1) * T_) * IN_ + tid];
        v.z = x[((size_t)(b0 + 2) * T_) * IN_ + tid];
        v.w = x[((size_t)(b0 + 3) * T_) * IN_ + tid];
        xts[tid] = v;
    }
    __syncthreads();

    float* ew0o = out + B_;
    float* ew1o = out + B_ + (size_t)B_ * T_;

    // persistent per-j registers for epilogue threads (tid<256)
    float4 i0 = z4, h0j = z4, hn = z4;
    float4 r[4];

    for (int t = 0; t < T_; ++t) {
        // ======== P1: attn0 || attn1 (1 mv4/thread); ew0; i0 (lower) ========
        if (wid < ROWS_) {
            const float* xf = (const float*)xts;
            const float* pf = (const float*)p0s;
            float s = xf[lane * 4 + wid] * wev0s[lane]
                    + pf[lane * 4 + wid] * wev0s[IN_ + lane];
            #pragma unroll
            for (int o = 16; o > 0; o >>= 1) s += __shfl_xor_sync(0xffffffffu, s, o);
            if (lane == 0) {
                float e = (t > 0) ? sigf(s + c_bev0) : 0.0f;
                scal[wid] = e;
                ew0o[(size_t)(b0 + wid) * T_ + t] = e;
            }
        }
        mv4(P1w, P1st, r);
        P1pb[0] = r[0]; P1pb[64] = r[1]; P1pb[128] = r[2]; P1pb[192] = r[3];
        if (tid < 256) {
            int j = tid;
            float bi = params[2 * 256 + j];
            i0 = make_float4(bi, bi, bi, bi);
            #pragma unroll
            for (int i = 0; i < IN_; ++i) {
                float w = Win0[i * H_ + j];
                float4 xv = xts[i];
                i0.x = fmaf(w, xv.x, i0.x); i0.y = fmaf(w, xv.y, i0.y);
                i0.z = fmaf(w, xv.z, i0.z); i0.w = fmaf(w, xv.w, i0.w);
            }
        }
        __syncthreads();                                    // full #1

        // ======== E1 (split): finalize a0 (lower) / a1 (upper) ========
        if (tid < 256) {
            int j = tid;
            float4 s0 = pb[j],        s1 = pb[256 + j];
            float4 s2 = pb[512 + j],  s3 = pb[768 + j];
            float ba = params[0 * 256 + j];
            float4 a0;
            a0.x = sigf(s0.x + s1.x + s2.x + s3.x + ba);
            a0.y = sigf(s0.y + s1.y + s2.y + s3.y + ba);
            a0.z = sigf(s0.z + s1.z + s2.z + s3.z + ba);
            a0.w = sigf(s0.w + s1.w + s2.w + s3.w + ba);
            h0j = h0s[j];
            gbuf0[j] = make_float4(h0j.x * a0.x, h0j.y * a0.y, h0j.z * a0.z, h0j.w * a0.w);
            if (j < IN_) p0s[j] = xts[j];                  // save x_t as prev
        } else {
            int j = tid - 256;
            float4 s0 = pb[1024 + j], s1 = pb[1280 + j];
            float4 s2 = pb[1536 + j], s3 = pb[1792 + j];
            float ba1 = params[3 * 256 + j];
            float4 a1;
            a1.x = sigf(s0.x + s1.x + s2.x + s3.x + ba1);
            a1.y = sigf(s0.y + s1.y + s2.y + s3.y + ba1);
            a1.z = sigf(s0.z + s1.z + s2.z + s3.z + ba1);
            a1.w = sigf(s0.w + s1.w + s2.w + s3.w + ba1);
            float4 h1v = h1s[j];
            gbuf1[j] = make_float4(h1v.x * a1.x, h1v.y * a1.y, h1v.z * a1.z, h1v.w * a1.w);
        }
        __syncthreads();                                    // full #2

        // ======== P2: rec0 || rec1 (1 mv4/thread) ========
        mv4(P2w, P2st, r);
        P2pb[0] = r[0]; P2pb[64] = r[1]; P2pb[128] = r[2]; P2pb[192] = r[3];
        __syncthreads();                                    // full #3

        // ======== zone2: layer-0 epilogue (lower only; upper waits) ========
        if (tid < 256) {
            int j = tid;
            float4 s0 = pb[j],        s1 = pb[256 + j];
            float4 s2 = pb[512 + j],  s3 = pb[768 + j];
            float br = params[1 * 256 + j];
            float r0x = s0.x + s1.x + s2.x + s3.x + br;
            float r0y = s0.y + s1.y + s2.y + s3.y + br;
            float r0z = s0.z + s1.z + s2.z + s3.z + br;
            float r0w = s0.w + s1.w + s2.w + s3.w + br;
            float rt0 = params[11 * 256 + j];
            const float e0 = 1.f + scal[0], e1 = 1.f + scal[1];
            const float e2 = 1.f + scal[2], e3 = 1.f + scal[3];
            float4 pre;
            pre.x = h0j.x + rt0 * (-h0j.x + tanhf(i0.x) + tanhf(r0x)) * e0;
            pre.y = h0j.y + rt0 * (-h0j.y + tanhf(i0.y) + tanhf(r0y)) * e1;
            pre.z = h0j.z + rt0 * (-h0j.z + tanhf(i0.z) + tanhf(r0z)) * e2;
            pre.w = h0j.w + rt0 * (-h0j.w + tanhf(i0.w) + tanhf(r0w)) * e3;
            tbuf[j] = pre;
            BAR256();
            if (wid < ROWS_) {
                const float* tf = (const float*)tbuf;
                float s = 0.f, ss = 0.f;
                #pragma unroll
                for (int m = 0; m < H_ / 32; ++m) {
                    float v = tf[(lane + 32 * m) * 4 + wid];
                    s += v; ss += v * v;
                }
                #pragma unroll
                for (int o = 16; o > 0; o >>= 1) {
                    s  += __shfl_xor_sync(0xffffffffu, s, o);
                    ss += __shfl_xor_sync(0xffffffffu, ss, o);
                }
                if (lane == 0) {
                    float mu = s * (1.0f / H_);
                    float var = ss * (1.0f / H_) - mu * mu;
                    scal[8 + wid]  = mu;
                    scal[12 + wid] = rsqrtf(var + EPS_C);
                }
            }
            BAR256();
            float g0 = params[7 * 256 + j], be0 = params[8 * 256 + j];
            hn.x = (pre.x - scal[8])  * scal[12] * g0 + be0;
            hn.y = (pre.y - scal[9])  * scal[13] * g0 + be0;
            hn.z = (pre.z - scal[10]) * scal[14] * g0 + be0;
            hn.w = (pre.w - scal[11]) * scal[15] * g0 + be0;
            h0ns[j] = hn;
            h0s[j]  = hn;
            float4 pv = p1s[j];
            float wa = params[13 * 256 + j], wb = params[14 * 256 + j];
            float4 part;
            part.x = hn.x * wa + pv.x * wb;
            part.y = hn.y * wa + pv.y * wb;
            part.z = hn.z * wa + pv.z * wb;
            part.w = hn.w * wa + pv.w * wb;
            #pragma unroll
            for (int o = 16; o > 0; o >>= 1) {
                part.x += __shfl_xor_sync(0xffffffffu, part.x, o);
                part.y += __shfl_xor_sync(0xffffffffu, part.y, o);
                part.z += __shfl_xor_sync(0xffffffffu, part.z, o);
                part.w += __shfl_xor_sync(0xffffffffu, part.w, o);
            }
            if (lane == 0) redbuf[wid] = part;
        }
        __syncthreads();                                    // full #4

        // ======== P3: ew1 final; inp1 || skip (1 mv4/thread) ========
        if (tid < ROWS_) {
            const float* rf = (const float*)redbuf;
            float s = c_bev1;
            #pragma unroll
            for (int w = 0; w < 8; ++w) s += rf[w * 4 + tid];
            float e = (t > 0) ? sigf(s) : 0.0f;
            scal[4 + tid] = e;
            ew1o[(size_t)(b0 + tid) * T_ + t] = e;
        }
        mv4(P3w, P3st, r);
        P3pb[0] = r[0]; P3pb[64] = r[1]; P3pb[128] = r[2]; P3pb[192] = r[3];
        __syncthreads();                                    // full #5

        // ======== E5: layer-1 update + LN1 + finalize; upper prefetches x ========
        if (tid < 256) {
            int j = tid;
            float4 i0q = pb[j],         i1q = pb[256 + j];
            float4 i2q = pb[512 + j],   i3q = pb[768 + j];
            float4 s0q = pb[1024 + j],  s1q = pb[1280 + j];
            float4 s2q = pb[1536 + j],  s3q = pb[1792 + j];
            float4 r0q = pb[2048 + j],  r1q = pb[2304 + j];
            float4 r2q = pb[2560 + j],  r3q = pb[2816 + j];
            float4 h1j = h1s[j];
            float bi = params[5 * 256 + j];
            float bs = params[6 * 256 + j];
            float br = params[4 * 256 + j];
            float i1x = i0q.x + i1q.x + i2q.x + i3q.x + bi;
            float i1y = i0q.y + i1q.y + i2q.y + i3q.y + bi;
            float i1z = i0q.z + i1q.z + i2q.z + i3q.z + bi;
            float i1w = i0q.w + i1q.w + i2q.w + i3q.w + bi;
            float4 skv;
            skv.x = s0q.x + s1q.x + s2q.x + s3q.x + bs;
            skv.y = s0q.y + s1q.y + s2q.y + s3q.y + bs;
            skv.z = s0q.z + s1q.z + s2q.z + s3q.z + bs;
            skv.w = s0q.w + s1q.w + s2q.w + s3q.w + bs;
            float r1x = r0q.x + r1q.x + r2q.x + r3q.x + br;
            float r1y = r0q.y + r1q.y + r2q.y + r3q.y + br;
            float r1z = r0q.z + r1q.z + r2q.z + r3q.z + br;
            float r1w = r0q.w + r1q.w + r2q.w + r3q.w + br;
            float rt1 = params[12 * 256 + j];
            const float e0 = 1.f + scal[4], e1 = 1.f + scal[5];
            const float e2 = 1.f + scal[6], e3 = 1.f + scal[7];
            float4 pre1;
            pre1.x = h1j.x + rt1 * (-h1j.x + tanhf(i1x) + tanhf(r1x)) * e0;
            pre1.y = h1j.y + rt1 * (-h1j.y + tanhf(i1y) + tanhf(r1y)) * e1;
            pre1.z = h1j.z + rt1 * (-h1j.z + tanhf(i1z) + tanhf(r1z)) * e2;
            pre1.w = h1j.w + rt1 * (-h1j.w + tanhf(i1w) + tanhf(r1w)) * e3;
            tbuf[j] = pre1;
            BAR256();
            if (wid < ROWS_) {
                const float* tf = (const float*)tbuf;
                float s = 0.f, ss = 0.f;
                #pragma unroll
                for (int m = 0; m < H_ / 32; ++m) {
                    float v = tf[(lane + 32 * m) * 4 + wid];
                    s += v; ss += v * v;
                }
                #pragma unroll
                for (int o = 16; o > 0; o >>= 1) {
                    s  += __shfl_xor_sync(0xffffffffu, s, o);
                    ss += __shfl_xor_sync(0xffffffffu, ss, o);
                }
                if (lane == 0) {
                    float mu = s * (1.0f / H_);
                    float var = ss * (1.0f / H_) - mu * mu;
                    scal[8 + wid]  = mu;
                    scal[12 + wid] = rsqrtf(var + EPS_C);
                }
            }
            BAR256();
            float g1 = params[9 * 256 + j], be1 = params[10 * 256 + j];
            float4 h1n;
            h1n.x = (pre1.x - scal[8])  * scal[12] * g1 + be1 + skv.x;
            h1n.y = (pre1.y - scal[9])  * scal[13] * g1 + be1 + skv.y;
            h1n.z = (pre1.z - scal[10]) * scal[14] * g1 + be1 + skv.z;
            h1n.w = (pre1.w - scal[11]) * scal[15] * g1 + be1 + skv.w;
            h1s[j] = h1n;
            p1s[j] = hn;
        } else if (tid < 256 + IN_ && t + 1 < T_) {
            int i = tid - 256;
            float4 v;
            v.x = x[((size_t)(b0 + 0) * T_ + (t + 1)) * IN_ + i];
            v.y = x[((size_t)(b0 + 1) * T_ + (t + 1)) * IN_ + i];
            v.z = x[((size_t)(b0 + 2) * T_ + (t + 1)) * IN_ + i];
            v.w = x[((size_t)(b0 + 3) * T_ + (t + 1)) * IN_ + i];
            xts[i] = v;
        }
        __syncthreads();                                    // full #6
    }

    // ---------- output head ----------
    if (tid < 256) {
        int j = tid;
        float wo = params[15 * 256 + j];
        float4 h = h1s[j];
        float4 part = make_float4(h.x * wo, h.y * wo, h.z * wo, h.w * wo);
        #pragma unroll
        for (int o = 16; o > 0; o >>= 1) {
            part.x += __shfl_xor_sync(0xffffffffu, part.x, o);
            part.y += __shfl_xor_sync(0xffffffffu, part.y, o);
            part.z += __shfl_xor_sync(0xffffffffu, part.z, o);
            part.w += __shfl_xor_sync(0xffffffffu, part.w, o);
        }
        if (lane == 0) redbuf[wid] = part;
    }
    __syncthreads();
    if (tid < ROWS_) {
        const float* rf = (const float*)redbuf;
        float s = c_bout;
        #pragma unroll
        for (int w = 0; w < 8; ++w) s += rf[w * 4 + tid];
        out[b0 + tid] = s;
    }
}

extern "C" void kernel_launch(void* const* d_in, const int* in_sizes, int n_in,
                              void* d_out, int out_size)
{
    (void)in_sizes; (void)n_in; (void)out_size;
    const float* x      = (const float*)d_in[0];
    const float* Win0   = (const float*)d_in[1];
    const float* bin0   = (const float*)d_in[2];
    const float* Wrec0  = (const float*)d_in[3];
    const float* brec0  = (const float*)d_in[4];
    const float* Wattn0 = (const float*)d_in[5];
    const float* battn0 = (const float*)d_in[6];
    const float* Wev0   = (const float*)d_in[7];
    const float* bev0   = (const float*)d_in[8];
    const float* tau0   = (const float*)d_in[9];
    const float* gamma0 = (const float*)d_in[10];
    const float* beta0  = (const float*)d_in[11];
    const float* Win1   = (const float*)d_in[12];
    const float* bin1   = (const float*)d_in[13];
    const float* Wrec1  = (const float*)d_in[14];
    const float* brec1  = (const float*)d_in[15];
    const float* Wattn1 = (const float*)d_in[16];
    const float* battn1 = (const float*)d_in[17];
    const float* Wev1   = (const float*)d_in[18];
    const float* bev1   = (const float*)d_in[19];
    const float* tau1   = (const float*)d_in[20];
    const float* gamma1 = (const float*)d_in[21];
    const float* beta1  = (const float*)d_in[22];
    const float* Wskip  = (const float*)d_in[23];
    const float* bskip  = (const float*)d_in[24];
    const float* Wout   = (const float*)d_in[25];
    const float* bout   = (const float*)d_in[26];

    cudaFuncSetAttribute(liquid_kernel,
                         cudaFuncAttributeMaxDynamicSharedMemorySize, SMEM_BYTES_);

    // Repack the six HxH fp32 matrices into k4-vectorized layout (exact fp32 copy).
    pack_weights<<<(6 * MATP_ + 255) / 256, 256>>>(
        Wattn0, Wrec0, Wattn1, Win1, Wskip, Wrec1);

    liquid_kernel<<<NBLK_, THREADS_, SMEM_BYTES_>>>(x,
        Win0, bin0, brec0, battn0, Wev0, bev0, tau0, gamma0, beta0,
        bin1, brec1, battn1, Wev1, bev1, tau1, gamma1, beta1,
        bskip, Wout, bout, (float*)d_out);
}

// round 15
// speedup vs baseline: 1.3817x; 1.3817x over previous
#include <cuda_runtime.h>
#include <math.h>

#define T_   2048
#define B_   512
#define IN_  32
#define H_   256
#define ROWS_ 4
#define NBLK_ (B_ / ROWS_)
#define THREADS_ 512
#define DT_C  0.1f
#define EPS_C 1e-5f

typedef unsigned long long u64;

// Repacked fp32 weights: 6 matrices [H x H] -> [H/4][H] float4:
// g_Wp[(m*64 + k4)*256 + j] = { W[4k4+0][j], W[4k4+1][j], W[4k4+2][j], W[4k4+3][j] }
// Order m: Wattn0, Wrec0, Wattn1, Win1, Wskip, Wrec1
#define MATP_ (64 * 256)
__device__ float4 g_Wp[6 * MATP_];

// Dynamic SMEM layout (float4 units):
//  [0,256)      h0s       [256,512)   h1s      [512,768)   p1s
//  [768,1024)   gbuf0     [1024,1280) gbuf1    [1280,1536) h0ns
//  [1536,1792)  tbuf
//  [1792,4864)  pb[4][3][256]
//  [4864,4896)  xts       [4896,4928) p0s      [4928,4936) redbuf
//  then floats: params[16][256], wev0s[64], scal[16]
#define SMEM_F4_  4936
#define SMEM_BYTES_ (SMEM_F4_ * 16 + 4096 * 4 + 64 * 4 + 16 * 4)

__device__ __forceinline__ float sigf(float z) { return 1.0f / (1.0f + expf(-z)); }

__device__ __forceinline__ u64 pack_dup(float w) {
    u64 r;
    unsigned int u = __float_as_uint(w);
    asm("mov.b64 %0, {%1, %1};" : "=l"(r) : "r"(u));
    return r;
}
__device__ __forceinline__ void unpack2(u64 v, float& a, float& b) {
    unsigned int lo, hi;
    asm("mov.b64 {%0, %1}, %2;" : "=r"(lo), "=r"(hi) : "l"(v));
    a = __uint_as_float(lo); b = __uint_as_float(hi);
}
__device__ __forceinline__ void fma2(u64& acc, u64 a, u64 b) {
    asm("fma.rn.f32x2 %0, %1, %2, %0;" : "+l"(acc) : "l"(a), "l"(b));
}

__global__ void pack_weights(const float* __restrict__ W0, const float* __restrict__ W1,
                             const float* __restrict__ W2, const float* __restrict__ W3,
                             const float* __restrict__ W4, const float* __restrict__ W5)
{
    int idx = blockIdx.x * blockDim.x + threadIdx.x;
    if (idx >= 6 * MATP_) return;
    const float* Ws[6] = {W0, W1, W2, W3, W4, W5};
    int m  = idx / MATP_;
    int r  = idx - m * MATP_;
    int k4 = r >> 8;
    int j  = r & 255;
    const float* W = Ws[m];
    g_Wp[idx] = make_float4(W[(4 * k4 + 0) * H_ + j], W[(4 * k4 + 1) * H_ + j],
                            W[(4 * k4 + 2) * H_ + j], W[(4 * k4 + 3) * H_ + j]);
}

// Quarter-K (64 k) matvec partial, 2 output columns, shared state loads.
__device__ __forceinline__ void mv2(const float4* __restrict__ wp0,
                                    const float4* __restrict__ wp1,
                                    const float4* st, float4& rA, float4& rB)
{
    u64 a01 = 0ull, a23 = 0ull, b01 = 0ull, b23 = 0ull;
    const ulonglong2* sp = (const ulonglong2*)st;
    #pragma unroll
    for (int k4 = 0; k4 < 16; ++k4) {
        float4 wA = __ldg(&wp0[k4 * H_]);
        float4 wB = __ldg(&wp1[k4 * H_]);
        ulonglong2 s0 = sp[4 * k4 + 0];
        ulonglong2 s1 = sp[4 * k4 + 1];
        ulonglong2 s2 = sp[4 * k4 + 2];
        ulonglong2 s3 = sp[4 * k4 + 3];
        u64 d;
        d = pack_dup(wA.x); fma2(a01, d, s0.x); fma2(a23, d, s0.y);
        d = pack_dup(wB.x); fma2(b01, d, s0.x); fma2(b23, d, s0.y);
        d = pack_dup(wA.y); fma2(a01, d, s1.x); fma2(a23, d, s1.y);
        d = pack_dup(wB.y); fma2(b01, d, s1.x); fma2(b23, d, s1.y);
        d = pack_dup(wA.z); fma2(a01, d, s2.x); fma2(a23, d, s2.y);
        d = pack_dup(wB.z); fma2(b01, d, s2.x); fma2(b23, d, s2.y);
        d = pack_dup(wA.w); fma2(a01, d, s3.x); fma2(a23, d, s3.y);
        d = pack_dup(wB.w); fma2(b01, d, s3.x); fma2(b23, d, s3.y);
    }
    unpack2(a01, rA.x, rA.y); unpack2(a23, rA.z, rA.w);
    unpack2(b01, rB.x, rB.y); unpack2(b23, rB.z, rB.w);
}

// Two matrices over the same state vector, 2 columns each (inp1 + skip).
__device__ __forceinline__ void mv2pair(const float4* __restrict__ wi0,
                                        const float4* __restrict__ wi1,
                                        const float4* __restrict__ ws0,
                                        const float4* __restrict__ ws1,
                                        const float4* st,
                                        float4& riA, float4& riB,
                                        float4& rsA, float4& rsB)
{
    u64 ia01 = 0ull, ia23 = 0ull, ib01 = 0ull, ib23 = 0ull;
    u64 sa01 = 0ull, sa23 = 0ull, sb01 = 0ull, sb23 = 0ull;
    const ulonglong2* sp = (const ulonglong2*)st;
    #pragma unroll
    for (int k4 = 0; k4 < 16; ++k4) {
        float4 wIA = __ldg(&wi0[k4 * H_]);
        float4 wIB = __ldg(&wi1[k4 * H_]);
        float4 wSA = __ldg(&ws0[k4 * H_]);
        float4 wSB = __ldg(&ws1[k4 * H_]);
        ulonglong2 s0 = sp[4 * k4 + 0];
        ulonglong2 s1 = sp[4 * k4 + 1];
        ulonglong2 s2 = sp[4 * k4 + 2];
        ulonglong2 s3 = sp[4 * k4 + 3];
        u64 d;
        d = pack_dup(wIA.x); fma2(ia01, d, s0.x); fma2(ia23, d, s0.y);
        d = pack_dup(wIB.x); fma2(ib01, d, s0.x); fma2(ib23, d, s0.y);
        d = pack_dup(wSA.x); fma2(sa01, d, s0.x); fma2(sa23, d, s0.y);
        d = pack_dup(wSB.x); fma2(sb01, d, s0.x); fma2(sb23, d, s0.y);
        d = pack_dup(wIA.y); fma2(ia01, d, s1.x); fma2(ia23, d, s1.y);
        d = pack_dup(wIB.y); fma2(ib01, d, s1.x); fma2(ib23, d, s1.y);
        d = pack_dup(wSA.y); fma2(sa01, d, s1.x); fma2(sa23, d, s1.y);
        d = pack_dup(wSB.y); fma2(sb01, d, s1.x); fma2(sb23, d, s1.y);
        d = pack_dup(wIA.z); fma2(ia01, d, s2.x); fma2(ia23, d, s2.y);
        d = pack_dup(wIB.z); fma2(ib01, d, s2.x); fma2(ib23, d, s2.y);
        d = pack_dup(wSA.z); fma2(sa01, d, s2.x); fma2(sa23, d, s2.y);
        d = pack_dup(wSB.z); fma2(sb01, d, s2.x); fma2(sb23, d, s2.y);
        d = pack_dup(wIA.w); fma2(ia01, d, s3.x); fma2(ia23, d, s3.y);
        d = pack_dup(wIB.w); fma2(ib01, d, s3.x); fma2(ib23, d, s3.y);
        d = pack_dup(wSA.w); fma2(sa01, d, s3.x); fma2(sa23, d, s3.y);
        d = pack_dup(wSB.w); fma2(sb01, d, s3.x); fma2(sb23, d, s3.y);
    }
    unpack2(ia01, riA.x, riA.y); unpack2(ia23, riA.z, riA.w);
    unpack2(ib01, riB.x, riB.y); unpack2(ib23, riB.z, riB.w);
    unpack2(sa01, rsA.x, rsA.y); unpack2(sa23, rsA.z, rsA.w);
    unpack2(sb01, rsB.x, rsB.y); unpack2(sb23, rsB.z, rsB.w);
}

__global__ void __launch_bounds__(THREADS_, 1)
liquid_kernel(const float* __restrict__ x,
              const float* __restrict__ Win0,  const float* __restrict__ bin0,
              const float* __restrict__ brec0, const float* __restrict__ battn0,
              const float* __restrict__ Wev0,  const float* __restrict__ bev0,
              const float* __restrict__ tau0,  const float* __restrict__ gamma0,
              const float* __restrict__ beta0,
              const float* __restrict__ bin1,  const float* __restrict__ brec1,
              const float* __restrict__ battn1,
              const float* __restrict__ Wev1,  const float* __restrict__ bev1,
              const float* __restrict__ tau1,  const float* __restrict__ gamma1,
              const float* __restrict__ beta1,
              const float* __restrict__ bskip,
              const float* __restrict__ Wout,  const float* __restrict__ bout,
              float* __restrict__ out)
{
    extern __shared__ float4 smem4[];
    float4* h0s   = smem4;
    float4* h1s   = smem4 + 256;
    float4* p1s   = smem4 + 512;
    float4* gbuf0 = smem4 + 768;
    float4* gbuf1 = smem4 + 1024;
    float4* h0ns  = smem4 + 1280;
    float4* tbuf  = smem4 + 1536;
    float4* pb    = smem4 + 1792;            // [4][3][256]
    float4* xts   = smem4 + 4864;            // 32
    float4* p0s   = smem4 + 4896;            // 32
    float4* redbuf = smem4 + 4928;           // 8 float4 = 16 float2
    float*  params = (float*)(smem4 + SMEM_F4_);  // 16*256
    float*  wev0s  = params + 4096;               // 64
    float*  scal   = wev0s + 64;                  // ew0[4], ew1[4], mu[4], rs[4]

    float2* h0s2  = (float2*)h0s;
    float2* h1s2  = (float2*)h1s;
    float2* p1s2  = (float2*)p1s;
    float2* h0ns2 = (float2*)h0ns;
    float2* tbuf2 = (float2*)tbuf;
    float2* pb2   = (float2*)pb;
    float2* xts2  = (float2*)xts;
    float2* red2  = (float2*)redbuf;

    const int tid  = threadIdx.x;
    const int lane = tid & 31;
    const int wid  = tid >> 5;
    const int q    = tid >> 7;        // K quarter 0..3 (matvec slots)
    const int jp   = tid & 127;       // column pair index
    const int j0   = jp, j1 = jp + 128;
    const int je   = tid & 255;       // epilogue j
    const int hv   = tid >> 8;        // epilogue component half (0: xy, 1: zw)
    const int b0   = blockIdx.x * ROWS_;

    const float c_bev0 = bev0[0], c_bev1 = bev1[0], c_bout = bout[0];

    // weight bases: matrix m, quarter q, cols j0/j1
    const int qofs = q * 16 * H_;
    const float4* Wa0_0 = g_Wp + 0 * MATP_ + qofs + j0;
    const float4* Wa0_1 = g_Wp + 0 * MATP_ + qofs + j1;
    const float4* Wr0_0 = g_Wp + 1 * MATP_ + qofs + j0;
    const float4* Wr0_1 = g_Wp + 1 * MATP_ + qofs + j1;
    const float4* Wa1_0 = g_Wp + 2 * MATP_ + qofs + j0;
    const float4* Wa1_1 = g_Wp + 2 * MATP_ + qofs + j1;
    const float4* Wi1_0 = g_Wp + 3 * MATP_ + qofs + j0;
    const float4* Wi1_1 = g_Wp + 3 * MATP_ + qofs + j1;
    const float4* Wsk_0 = g_Wp + 4 * MATP_ + qofs + j0;
    const float4* Wsk_1 = g_Wp + 4 * MATP_ + qofs + j1;
    const float4* Wr1_0 = g_Wp + 5 * MATP_ + qofs + j0;
    const float4* Wr1_1 = g_Wp + 5 * MATP_ + qofs + j1;

    const float4 z4 = make_float4(0.f, 0.f, 0.f, 0.f);
    if (tid < 256) {
        int j = tid;
        params[0 * 256 + j]  = battn0[j];
        params[1 * 256 + j]  = brec0[j];
        params[2 * 256 + j]  = bin0[j];
        params[3 * 256 + j]  = battn1[j];
        params[4 * 256 + j]  = brec1[j];
        params[5 * 256 + j]  = bin1[j];
        params[6 * 256 + j]  = bskip[j];
        params[7 * 256 + j]  = gamma0[j];
        params[8 * 256 + j]  = beta0[j];
        params[9 * 256 + j]  = gamma1[j];
        params[10 * 256 + j] = beta1[j];
        params[11 * 256 + j] = DT_C / fminf(fmaxf(tau0[j], 0.1f), 10.0f);
        params[12 * 256 + j] = DT_C / fminf(fmaxf(tau1[j], 0.1f), 10.0f);
        params[13 * 256 + j] = Wev1[j];
        params[14 * 256 + j] = Wev1[H_ + j];
        params[15 * 256 + j] = Wout[j];
        h0s[j] = z4; h1s[j] = z4; p1s[j] = z4;
    }
    if (tid < 2 * IN_) wev0s[tid] = Wev0[tid];
    if (tid < IN_) {
        p0s[tid] = z4;
        float4 v;
        v.x = x[((size_t)(b0 + 0) * T_) * IN_ + tid];
        v.y = x[((size_t)(b0 + 1) * T_) * IN_ + tid];
        v.z = x[((size_t)(b0 + 2) * T_) * IN_ + tid];
        v.w = x[((size_t)(b0 + 3) * T_) * IN_ + tid];
        xts[tid] = v;
    }
    __syncthreads();

    float* ew0o = out + B_;
    float* ew1o = out + B_ + (size_t)B_ * T_;

    // persistent per-(je,hv) epilogue registers
    float2 i0h = make_float2(0.f, 0.f);
    float2 hn2 = make_float2(0.f, 0.f);

    for (int t = 0; t < T_; ++t) {
        // ======== P1: attn0 + attn1 partials (all); ew0 (warps 0-3); i0 half (all) ========
        if (wid < ROWS_) {
            const float* xf = (const float*)xts;
            const float* pf = (const float*)p0s;
            float s = xf[lane * 4 + wid] * wev0s[lane]
                    + pf[lane * 4 + wid] * wev0s[IN_ + lane];
            #pragma unroll
            for (int o = 16; o > 0; o >>= 1) s += __shfl_xor_sync(0xffffffffu, s, o);
            if (lane == 0) {
                float e = (t > 0) ? sigf(s + c_bev0) : 0.0f;
                scal[wid] = e;
                ew0o[(size_t)(b0 + wid) * T_ + t] = e;
            }
        }
        {
            float4 pA, pB;
            mv2(Wa0_0, Wa0_1, h0s + q * 64, pA, pB);
            pb[(q * 3 + 0) * 256 + j0] = pA;
            pb[(q * 3 + 0) * 256 + j1] = pB;
            mv2(Wa1_0, Wa1_1, h1s + q * 64, pA, pB);
            pb[(q * 3 + 1) * 256 + j0] = pA;
            pb[(q * 3 + 1) * 256 + j1] = pB;
        }
        {
            float bi = params[2 * 256 + je];
            i0h = make_float2(bi, bi);
            #pragma unroll
            for (int i = 0; i < IN_; ++i) {
                float w = Win0[i * H_ + je];
                float2 xv = xts2[2 * i + hv];
                i0h.x = fmaf(w, xv.x, i0h.x);
                i0h.y = fmaf(w, xv.y, i0h.y);
            }
        }
        __syncthreads();                                    // full #1

        // ======== E1 (split): finalize a0 (lower) / a1 (upper) ========
        if (tid < 256) {
            int j = tid;
            float4 s0 = pb[j],        s1 = pb[768 + j];
            float4 s2 = pb[1536 + j], s3 = pb[2304 + j];
            float ba = params[0 * 256 + j];
            float4 a0;
            a0.x = sigf(s0.x + s1.x + s2.x + s3.x + ba);
            a0.y = sigf(s0.y + s1.y + s2.y + s3.y + ba);
            a0.z = sigf(s0.z + s1.z + s2.z + s3.z + ba);
            a0.w = sigf(s0.w + s1.w + s2.w + s3.w + ba);
            float4 h0v = h0s[j];
            gbuf0[j] = make_float4(h0v.x * a0.x, h0v.y * a0.y, h0v.z * a0.z, h0v.w * a0.w);
            if (j < IN_) p0s[j] = xts[j];                  // save x_t as prev
        } else {
            int j = tid - 256;
            float4 s0 = pb[256 + j],  s1 = pb[1024 + j];
            float4 s2 = pb[1792 + j], s3 = pb[2560 + j];
            float ba1 = params[3 * 256 + j];
            float4 a1;
            a1.x = sigf(s0.x + s1.x + s2.x + s3.x + ba1);
            a1.y = sigf(s0.y + s1.y + s2.y + s3.y + ba1);
            a1.z = sigf(s0.z + s1.z + s2.z + s3.z + ba1);
            a1.w = sigf(s0.w + s1.w + s2.w + s3.w + ba1);
            float4 h1v = h1s[j];
            gbuf1[j] = make_float4(h1v.x * a1.x, h1v.y * a1.y, h1v.z * a1.z, h1v.w * a1.w);
        }
        __syncthreads();                                    // full #2

        // ======== P2: rec0 -> region0, rec1 -> region2 (all threads) ========
        {
            float4 pA, pB;
            mv2(Wr0_0, Wr0_1, gbuf0 + q * 64, pA, pB);
            pb[(q * 3 + 0) * 256 + j0] = pA;
            pb[(q * 3 + 0) * 256 + j1] = pB;
            mv2(Wr1_0, Wr1_1, gbuf1 + q * 64, pA, pB);
            pb[(q * 3 + 2) * 256 + j0] = pA;
            pb[(q * 3 + 2) * 256 + j1] = pB;
        }
        __syncthreads();                                    // full #3

        // ======== E2a (all 512, component-split): layer-0 update ========
        {
            float2 s0 = pb2[2 * (0 * 768 + je) + hv];
            float2 s1 = pb2[2 * (1 * 768 + je) + hv];
            float2 s2 = pb2[2 * (2 * 768 + je) + hv];
            float2 s3 = pb2[2 * (3 * 768 + je) + hv];
            float br = params[1 * 256 + je];
            float r0a = s0.x + s1.x + s2.x + s3.x + br;
            float r0b = s0.y + s1.y + s2.y + s3.y + br;
            float2 h0 = h0s2[2 * je + hv];
            float rt0 = params[11 * 256 + je];
            const float ea = 1.f + scal[2 * hv + 0];
            const float eb = 1.f + scal[2 * hv + 1];
            float2 pre;
            pre.x = h0.x + rt0 * (-h0.x + tanhf(i0h.x) + tanhf(r0a)) * ea;
            pre.y = h0.y + rt0 * (-h0.y + tanhf(i0h.y) + tanhf(r0b)) * eb;
            tbuf2[2 * je + hv] = pre;
            __syncthreads();                                // stats in
            if (wid < ROWS_) {
                const float* tf = (const float*)tbuf;
                float s = 0.f, ss = 0.f;
                #pragma unroll
                for (int m = 0; m < H_ / 32; ++m) {
                    float v = tf[(lane + 32 * m) * 4 + wid];
                    s += v; ss += v * v;
                }
                #pragma unroll
                for (int o = 16; o > 0; o >>= 1) {
                    s  += __shfl_xor_sync(0xffffffffu, s, o);
                    ss += __shfl_xor_sync(0xffffffffu, ss, o);
                }
                if (lane == 0) {
                    float mu = s * (1.0f / H_);
                    float var = ss * (1.0f / H_) - mu * mu;
                    scal[8 + wid]  = mu;
                    scal[12 + wid] = rsqrtf(var + EPS_C);
                }
            }
            __syncthreads();                                // stats out
            float g0 = params[7 * 256 + je], be0 = params[8 * 256 + je];
            hn2.x = (pre.x - scal[8 + 2 * hv]) * scal[12 + 2 * hv] * g0 + be0;
            hn2.y = (pre.y - scal[9 + 2 * hv]) * scal[13 + 2 * hv] * g0 + be0;
            h0ns2[2 * je + hv] = hn2;
            h0s2[2 * je + hv]  = hn2;
            float2 pv = p1s2[2 * je + hv];
            float wa = params[13 * 256 + je], wb = params[14 * 256 + je];
            float2 part;
            part.x = hn2.x * wa + pv.x * wb;
            part.y = hn2.y * wa + pv.y * wb;
            #pragma unroll
            for (int o = 16; o > 0; o >>= 1) {
                part.x += __shfl_xor_sync(0xffffffffu, part.x, o);
                part.y += __shfl_xor_sync(0xffffffffu, part.y, o);
            }
            if (lane == 0) red2[wid] = part;
        }
        __syncthreads();                                    // full #4

        // ======== P3: ew1 final; inp1 + skip partials (all) ========
        if (tid < ROWS_) {
            float s = c_bev1;
            int base = (tid >= 2) ? 8 : 0;
            int sel  = tid & 1;
            #pragma unroll
            for (int w = 0; w < 8; ++w) {
                float2 v = red2[base + w];
                s += sel ? v.y : v.x;
            }
            float e = (t > 0) ? sigf(s) : 0.0f;
            scal[4 + tid] = e;
            ew1o[(size_t)(b0 + tid) * T_ + t] = e;
        }
        {
            float4 iA, iB, sA, sB;
            mv2pair(Wi1_0, Wi1_1, Wsk_0, Wsk_1, h0ns + q * 64, iA, iB, sA, sB);
            pb[(q * 3 + 0) * 256 + j0] = iA;
            pb[(q * 3 + 0) * 256 + j1] = iB;
            pb[(q * 3 + 1) * 256 + j0] = sA;
            pb[(q * 3 + 1) * 256 + j1] = sB;
        }
        __syncthreads();                                    // full #5

        // ======== E5 (all 512, component-split): layer-1 update + LN1 ========
        {
            float2 i0q = pb2[2 * (0 * 768 + je) + hv];
            float2 i1q = pb2[2 * (1 * 768 + je) + hv];
            float2 i2q = pb2[2 * (2 * 768 + je) + hv];
            float2 i3q = pb2[2 * (3 * 768 + je) + hv];
            float2 s0q = pb2[2 * (0 * 768 + 256 + je) + hv];
            float2 s1q = pb2[2 * (1 * 768 + 256 + je) + hv];
            float2 s2q = pb2[2 * (2 * 768 + 256 + je) + hv];
            float2 s3q = pb2[2 * (3 * 768 + 256 + je) + hv];
            float2 r0q = pb2[2 * (0 * 768 + 512 + je) + hv];
            float2 r1q = pb2[2 * (1 * 768 + 512 + je) + hv];
            float2 r2q = pb2[2 * (2 * 768 + 512 + je) + hv];
            float2 r3q = pb2[2 * (3 * 768 + 512 + je) + hv];
            float2 h1 = h1s2[2 * je + hv];
            float bi = params[5 * 256 + je];
            float bs = params[6 * 256 + je];
            float br = params[4 * 256 + je];
            float i1a = i0q.x + i1q.x + i2q.x + i3q.x + bi;
            float i1b = i0q.y + i1q.y + i2q.y + i3q.y + bi;
            float2 skv;
            skv.x = s0q.x + s1q.x + s2q.x + s3q.x + bs;
            skv.y = s0q.y + s1q.y + s2q.y + s3q.y + bs;
            float r1a = r0q.x + r1q.x + r2q.x + r3q.x + br;
            float r1b = r0q.y + r1q.y + r2q.y + r3q.y + br;
            float rt1 = params[12 * 256 + je];
            const float ea = 1.f + scal[4 + 2 * hv + 0];
            const float eb = 1.f + scal[4 + 2 * hv + 1];
            float2 pre1;
            pre1.x = h1.x + rt1 * (-h1.x + tanhf(i1a) + tanhf(r1a)) * ea;
            pre1.y = h1.y + rt1 * (-h1.y + tanhf(i1b) + tanhf(r1b)) * eb;
            tbuf2[2 * je + hv] = pre1;
            __syncthreads();                                // stats in
            if (wid < ROWS_) {
                const float* tf = (const float*)tbuf;
                float s = 0.f, ss = 0.f;
                #pragma unroll
                for (int m = 0; m < H_ / 32; ++m) {
                    float v = tf[(lane + 32 * m) * 4 + wid];
                    s += v; ss += v * v;
                }
                #pragma unroll
                for (int o = 16; o > 0; o >>= 1) {
                    s  += __shfl_xor_sync(0xffffffffu, s, o);
                    ss += __shfl_xor_sync(0xffffffffu, ss, o);
                }
                if (lane == 0) {
                    float mu = s * (1.0f / H_);
                    float var = ss * (1.0f / H_) - mu * mu;
                    scal[8 + wid]  = mu;
                    scal[12 + wid] = rsqrtf(var + EPS_C);
                }
            }
            __syncthreads();                                // stats out
            float g1 = params[9 * 256 + je], be1 = params[10 * 256 + je];
            float2 h1n;
            h1n.x = (pre1.x - scal[8 + 2 * hv]) * scal[12 + 2 * hv] * g1 + be1 + skv.x;
            h1n.y = (pre1.y - scal[9 + 2 * hv]) * scal[13 + 2 * hv] * g1 + be1 + skv.y;
            h1s2[2 * je + hv] = h1n;
            p1s2[2 * je + hv] = hn2;
            if (tid < IN_ && t + 1 < T_) {
                float4 v;
                v.x = x[((size_t)(b0 + 0) * T_ + (t + 1)) * IN_ + tid];
                v.y = x[((size_t)(b0 + 1) * T_ + (t + 1)) * IN_ + tid];
                v.z = x[((size_t)(b0 + 2) * T_ + (t + 1)) * IN_ + tid];
                v.w = x[((size_t)(b0 + 3) * T_ + (t + 1)) * IN_ + tid];
                xts[tid] = v;
            }
        }
        __syncthreads();                                    // full #6
    }

    // ---------- output head ----------
    if (tid < 256) {
        int j = tid;
        float wo = params[15 * 256 + j];
        float4 h = h1s[j];
        float4 part = make_float4(h.x * wo, h.y * wo, h.z * wo, h.w * wo);
        #pragma unroll
        for (int o = 16; o > 0; o >>= 1) {
            part.x += __shfl_xor_sync(0xffffffffu, part.x, o);
            part.y += __shfl_xor_sync(0xffffffffu, part.y, o);
            part.z += __shfl_xor_sync(0xffffffffu, part.z, o);
            part.w += __shfl_xor_sync(0xffffffffu, part.w, o);
        }
        if (lane == 0) redbuf[wid] = part;
    }
    __syncthreads();
    if (tid < ROWS_) {
        const float* rf = (const float*)redbuf;
        float s = c_bout;
        #pragma unroll
        for (int w = 0; w < 8; ++w) s += rf[w * 4 + tid];
        out[b0 + tid] = s;
    }
}

extern "C" void kernel_launch(void* const* d_in, const int* in_sizes, int n_in,
                              void* d_out, int out_size)
{
    (void)in_sizes; (void)n_in; (void)out_size;
    const float* x      = (const float*)d_in[0];
    const float* Win0   = (const float*)d_in[1];
    const float* bin0   = (const float*)d_in[2];
    const float* Wrec0  = (const float*)d_in[3];
    const float* brec0  = (const float*)d_in[4];
    const float* Wattn0 = (const float*)d_in[5];
    const float* battn0 = (const float*)d_in[6];
    const float* Wev0   = (const float*)d_in[7];
    const float* bev0   = (const float*)d_in[8];
    const float* tau0   = (const float*)d_in[9];
    const float* gamma0 = (const float*)d_in[10];
    const float* beta0  = (const float*)d_in[11];
    const float* Win1   = (const float*)d_in[12];
    const float* bin1   = (const float*)d_in[13];
    const float* Wrec1  = (const float*)d_in[14];
    const float* brec1  = (const float*)d_in[15];
    const float* Wattn1 = (const float*)d_in[16];
    const float* battn1 = (const float*)d_in[17];
    const float* Wev1   = (const float*)d_in[18];
    const float* bev1   = (const float*)d_in[19];
    const float* tau1   = (const float*)d_in[20];
    const float* gamma1 = (const float*)d_in[21];
    const float* beta1  = (const float*)d_in[22];
    const float* Wskip  = (const float*)d_in[23];
    const float* bskip  = (const float*)d_in[24];
    const float* Wout   = (const float*)d_in[25];
    const float* bout   = (const float*)d_in[26];

    cudaFuncSetAttribute(liquid_kernel,
                         cudaFuncAttributeMaxDynamicSharedMemorySize, SMEM_BYTES_);

    // Repack the six HxH fp32 matrices into k4-vectorized layout (exact fp32 copy).
    pack_weights<<<(6 * MATP_ + 255) / 256, 256>>>(
        Wattn0, Wrec0, Wattn1, Win1, Wskip, Wrec1);

    liquid_kernel<<<NBLK_, THREADS_, SMEM_BYTES_>>>(x,
        Win0, bin0, brec0, battn0, Wev0, bev0, tau0, gamma0, beta0,
        bin1, brec1, battn1, Wev1, bev1, tau1, gamma1, beta1,
        bskip, Wout, bout, (float*)d_out);
}